// round 1
// baseline (speedup 1.0000x reference)
#include <cuda_runtime.h>

#define BB 4
#define NN 4096
#define FF 32
#define KK 6
#define OO 128

#define BM 128
#define BKT 32

// Scratch ping-pong buffers for Chebyshev terms: [B, N, F] each (2 MB)
__device__ float g_bufA[BB * NN * FF];
__device__ float g_bufB[BB * NN * FF];

// ---------------------------------------------------------------------------
// GEMM: Tnew[b, :, :] = alpha * L[b] @ Tprev[b] + beta * Tpp[b]
// L: [B, N, N], Tprev/Tpp/Tnew: [B, N, F]
// Block: BM=128 rows x F=32 cols, 256 threads, 4x4 register tile.
// ---------------------------------------------------------------------------
__global__ __launch_bounds__(256) void cheb_gemm(
    const float* __restrict__ Lmat,
    const float* __restrict__ Tprev,
    const float* __restrict__ Tpp,
    float* __restrict__ Tnew,
    float alpha, float beta)
{
    __shared__ float As[2][BKT][BM + 4];   // [k][row], padded (132 floats -> 16B aligned rows)
    __shared__ float Bs[2][BKT][FF];       // [k][f]

    const int b    = blockIdx.y;
    const int row0 = blockIdx.x * BM;

    const float* Lb = Lmat + ((size_t)b * NN + row0) * NN;
    const float* Tp = Tprev + (size_t)b * NN * FF;

    const int tid = threadIdx.x;
    const int tx  = tid & 7;     // 0..7  -> f group (4 cols each)
    const int ty  = tid >> 3;    // 0..31 -> row group (4 rows each)

    // loader mapping (same for A and B tiles)
    const int lr = tid >> 3;     // 0..31
    const int lc = tid & 7;      // 0..7 (float4 group)

    float acc[4][4];
#pragma unroll
    for (int i = 0; i < 4; i++)
#pragma unroll
        for (int j = 0; j < 4; j++) acc[i][j] = 0.0f;

    float4 aReg[4];
    float4 bReg;

    const int NT = NN / BKT;   // 128 k-tiles

    // ---- load tile 0 into registers ----
#pragma unroll
    for (int p = 0; p < 4; p++) {
        const int r = lr + p * 32;
        aReg[p] = *reinterpret_cast<const float4*>(Lb + (size_t)r * NN + lc * 4);
    }
    bReg = *reinterpret_cast<const float4*>(Tp + (size_t)lr * FF + lc * 4);

    // ---- store tile 0 into smem buf 0 ----
    {
#pragma unroll
        for (int p = 0; p < 4; p++) {
            const int r = lr + p * 32;
            As[0][lc * 4 + 0][r] = aReg[p].x;
            As[0][lc * 4 + 1][r] = aReg[p].y;
            As[0][lc * 4 + 2][r] = aReg[p].z;
            As[0][lc * 4 + 3][r] = aReg[p].w;
        }
        *reinterpret_cast<float4*>(&Bs[0][lr][lc * 4]) = bReg;
    }
    __syncthreads();

    int buf = 0;
    for (int kt = 0; kt < NT; kt++) {
        // prefetch next tile into registers (hidden under compute)
        if (kt + 1 < NT) {
            const int k0 = (kt + 1) * BKT;
#pragma unroll
            for (int p = 0; p < 4; p++) {
                const int r = lr + p * 32;
                aReg[p] = *reinterpret_cast<const float4*>(Lb + (size_t)r * NN + k0 + lc * 4);
            }
            bReg = *reinterpret_cast<const float4*>(Tp + (size_t)(k0 + lr) * FF + lc * 4);
        }

        // compute on current buffer
        {
            const float(*A)[BM + 4] = As[buf];
            const float(*Bt)[FF]    = Bs[buf];
#pragma unroll
            for (int k = 0; k < BKT; k++) {
                const float4 a  = *reinterpret_cast<const float4*>(&A[k][ty * 4]);
                const float4 bv = *reinterpret_cast<const float4*>(&Bt[k][tx * 4]);
                acc[0][0] += a.x * bv.x; acc[0][1] += a.x * bv.y;
                acc[0][2] += a.x * bv.z; acc[0][3] += a.x * bv.w;
                acc[1][0] += a.y * bv.x; acc[1][1] += a.y * bv.y;
                acc[1][2] += a.y * bv.z; acc[1][3] += a.y * bv.w;
                acc[2][0] += a.z * bv.x; acc[2][1] += a.z * bv.y;
                acc[2][2] += a.z * bv.z; acc[2][3] += a.z * bv.w;
                acc[3][0] += a.w * bv.x; acc[3][1] += a.w * bv.y;
                acc[3][2] += a.w * bv.z; acc[3][3] += a.w * bv.w;
            }
        }

        // store prefetched tile to the other buffer
        if (kt + 1 < NT) {
            const int nb = buf ^ 1;
#pragma unroll
            for (int p = 0; p < 4; p++) {
                const int r = lr + p * 32;
                As[nb][lc * 4 + 0][r] = aReg[p].x;
                As[nb][lc * 4 + 1][r] = aReg[p].y;
                As[nb][lc * 4 + 2][r] = aReg[p].z;
                As[nb][lc * 4 + 3][r] = aReg[p].w;
            }
            *reinterpret_cast<float4*>(&Bs[nb][lr][lc * 4]) = bReg;
            __syncthreads();
            buf = nb;
        }
    }

    // epilogue: Tnew = alpha*acc + beta*Tpp  (float4 stores, same-index read of Tpp)
#pragma unroll
    for (int i = 0; i < 4; i++) {
        const int row  = row0 + ty * 4 + i;
        const size_t o = ((size_t)b * NN + row) * FF + tx * 4;
        float4 v;
        v.x = alpha * acc[i][0];
        v.y = alpha * acc[i][1];
        v.z = alpha * acc[i][2];
        v.w = alpha * acc[i][3];
        if (beta != 0.0f) {
            const float4 p = *reinterpret_cast<const float4*>(Tpp + o);
            v.x += beta * p.x; v.y += beta * p.y;
            v.z += beta * p.z; v.w += beta * p.w;
        }
        *reinterpret_cast<float4*>(Tnew + o) = v;
    }
}

// ---------------------------------------------------------------------------
// Projection: out[b,n,:] (+)= theta[k] * T[b,n,:] @ W[k]   (W[k]: [F, O])
// 128 threads (one per o), 16 rows per block, W column in registers.
// ---------------------------------------------------------------------------
#define PROWS 16

__global__ __launch_bounds__(128) void cheb_proj(
    const float* __restrict__ T,
    const float* __restrict__ W,
    const float* __restrict__ theta,
    int k,
    float* __restrict__ out,
    int accumulate)
{
    __shared__ float Ts[PROWS][FF];

    const int o = threadIdx.x;                     // 0..127
    const size_t rowBase = (size_t)blockIdx.x * PROWS;  // row in [0, B*N)
    const float* Wk = W + (size_t)k * FF * OO;

    float w[FF];
#pragma unroll
    for (int f = 0; f < FF; f++) w[f] = Wk[(size_t)f * OO + o];

    // load PROWS x FF tile of T (coalesced)
    for (int i = threadIdx.x; i < PROWS * FF; i += 128) {
        (&Ts[0][0])[i] = T[rowBase * FF + i];
    }
    __syncthreads();

    const float th = theta[k];
#pragma unroll
    for (int r = 0; r < PROWS; r++) {
        float acc = 0.0f;
#pragma unroll
        for (int f = 0; f < FF; f++) acc += Ts[r][f] * w[f];
        const size_t oidx = (rowBase + r) * OO + o;
        float v = th * acc;
        if (accumulate) v += out[oidx];
        out[oidx] = v;
    }
}

// ---------------------------------------------------------------------------
// Launcher
// ---------------------------------------------------------------------------
extern "C" void kernel_launch(void* const* d_in, const int* in_sizes, int n_in,
                              void* d_out, int out_size)
{
    // Identify inputs by element count (all distinct):
    //   x: B*N*F = 524288, L: B*N*N = 67108864, W: K*F*O = 24576, theta: K = 6
    const float* x = nullptr;
    const float* Lm = nullptr;
    const float* W = nullptr;
    const float* theta = nullptr;
    for (int i = 0; i < n_in; i++) {
        switch (in_sizes[i]) {
            case BB * NN * FF: x = (const float*)d_in[i]; break;
            case BB * NN * NN: Lm = (const float*)d_in[i]; break;
            case KK * FF * OO: W = (const float*)d_in[i]; break;
            case KK:           theta = (const float*)d_in[i]; break;
            default: break;
        }
    }
    float* out = (float*)d_out;

    float* bufA = nullptr;
    float* bufB = nullptr;
    cudaGetSymbolAddress((void**)&bufA, g_bufA);
    cudaGetSymbolAddress((void**)&bufB, g_bufB);

    const dim3 gGrid(NN / BM, BB);
    const dim3 gBlk(256);
    const dim3 pGrid((BB * NN) / PROWS);
    const dim3 pBlk(128);

    // k = 0: out = theta0 * x @ W0
    cheb_proj<<<pGrid, pBlk>>>(x, W, theta, 0, out, 0);

    // T1 = L @ x
    cheb_gemm<<<gGrid, gBlk>>>(Lm, x, x, bufA, 1.0f, 0.0f);
    cheb_proj<<<pGrid, pBlk>>>(bufA, W, theta, 1, out, 1);

    // T2 = 2 L @ T1 - x
    cheb_gemm<<<gGrid, gBlk>>>(Lm, bufA, x, bufB, 2.0f, -1.0f);
    cheb_proj<<<pGrid, pBlk>>>(bufB, W, theta, 2, out, 1);

    // T3 = 2 L @ T2 - T1   (in-place over bufA: beta term is same-index)
    cheb_gemm<<<gGrid, gBlk>>>(Lm, bufB, bufA, bufA, 2.0f, -1.0f);
    cheb_proj<<<pGrid, pBlk>>>(bufA, W, theta, 3, out, 1);

    // T4 = 2 L @ T3 - T2
    cheb_gemm<<<gGrid, gBlk>>>(Lm, bufA, bufB, bufB, 2.0f, -1.0f);
    cheb_proj<<<pGrid, pBlk>>>(bufB, W, theta, 4, out, 1);

    // T5 = 2 L @ T4 - T3
    cheb_gemm<<<gGrid, gBlk>>>(Lm, bufB, bufA, bufA, 2.0f, -1.0f);
    cheb_proj<<<pGrid, pBlk>>>(bufA, W, theta, 5, out, 1);
}

// round 3
// speedup vs baseline: 2.6788x; 2.6788x over previous
#include <cuda_runtime.h>
#include <cuda_bf16.h>
#include <cstdint>

#define BB 4
#define NN 4096
#define FF 32
#define KK 6
#define OO 128

// ---- GEMM tiling ----
#define BM 64                   // rows per CTA (4 warps x 16 rows)
#define KC 32                   // k per chunk
#define NSTAGE 4
#define NCHUNK (NN / KC)        // 128

#define AROWF 40                                // A smem row stride in floats (conflict-free, 160B)
#define AROWB (AROWF * 4)
#define A_BYTES (BM * AROWB)                    // 10240
#define BROWB 80                                // B smem row stride bytes (32 x bf16 = 64B data + pad)
#define B_BYTES (FF * BROWB)                    // 2560
#define BHI_OFF A_BYTES
#define BLO_OFF (A_BYTES + B_BYTES)
#define STAGE_BYTES (A_BYTES + 2 * B_BYTES)     // 15360
#define SMEM_TOTAL (NSTAGE * STAGE_BYTES)       // 61440

// Scratch: Chebyshev term ping-pong (fp32) + transposed bf16 hi/lo of Tprev
__device__ float g_bufA[BB * NN * FF];
__device__ float g_bufB[BB * NN * FF];
__device__ __nv_bfloat16 g_bt_hi[BB * FF * NN];   // [b][f][n]
__device__ __nv_bfloat16 g_bt_lo[BB * FF * NN];

__device__ __forceinline__ uint32_t smem_u32(const void* p) {
    uint32_t a;
    asm("{ .reg .u64 t; cvta.to.shared.u64 t, %1; cvt.u32.u64 %0, t; }" : "=r"(a) : "l"(p));
    return a;
}

__device__ __forceinline__ void cp16(uint32_t dst, const void* src) {
    asm volatile("cp.async.cg.shared.global [%0], [%1], 16;" :: "r"(dst), "l"(src));
}
#define CP_COMMIT() asm volatile("cp.async.commit_group;" ::: "memory")
#define CP_WAIT(n)  asm volatile("cp.async.wait_group %0;" :: "n"(n) : "memory")

// rn-bf16 hi/lo split of a float pair; low half of packed reg = first element (k), high = k+1
__device__ __forceinline__ void split2(float x, float y, uint32_t& hi, uint32_t& lo) {
    asm("cvt.rn.bf16x2.f32 %0, %1, %2;" : "=r"(hi) : "f"(y), "f"(x));
    const float h0 = __uint_as_float(hi << 16);
    const float h1 = __uint_as_float(hi & 0xFFFF0000u);
    const float l0 = x - h0;
    const float l1 = y - h1;
    asm("cvt.rn.bf16x2.f32 %0, %1, %2;" : "=r"(lo) : "f"(l1), "f"(l0));
}

__device__ __forceinline__ void mma16816(float* c,
                                         uint32_t a0, uint32_t a1, uint32_t a2, uint32_t a3,
                                         uint32_t b0, uint32_t b1) {
    asm volatile(
        "mma.sync.aligned.m16n8k16.row.col.f32.bf16.bf16.f32 "
        "{%0,%1,%2,%3}, {%4,%5,%6,%7}, {%8,%9}, {%0,%1,%2,%3};"
        : "+f"(c[0]), "+f"(c[1]), "+f"(c[2]), "+f"(c[3])
        : "r"(a0), "r"(a1), "r"(a2), "r"(a3), "r"(b0), "r"(b1));
}

// ---------------------------------------------------------------------------
// Prep: Tprev [b][n][f] fp32 -> transposed bf16 hi/lo [b][f][n]
// ---------------------------------------------------------------------------
__global__ __launch_bounds__(256) void prep_b(
    const float* __restrict__ T,
    __nv_bfloat16* __restrict__ hi,
    __nv_bfloat16* __restrict__ lo)
{
    const int idx = blockIdx.x * 256 + threadIdx.x;     // [b][f][n] flat
    const int n = idx & (NN - 1);
    const int f = (idx >> 12) & (FF - 1);
    const int b = idx >> 17;
    const float a = T[((size_t)b * NN + n) * FF + f];
    const __nv_bfloat16 h = __float2bfloat16_rn(a);
    hi[idx] = h;
    lo[idx] = __float2bfloat16_rn(a - __bfloat162float(h));
}

// ---------------------------------------------------------------------------
// HMMA GEMM: Tnew[b,row0..row0+63,:] = alpha * L[b] @ Tprev[b] + beta * Tpp
//   A: fp32 streamed via cp.async, split to bf16 hi/lo inline
//   B: pre-split bf16 hi/lo, transposed [f][n], streamed via cp.async
//   3-product bf16 split MMA, fp32 register accumulators
// ---------------------------------------------------------------------------
__global__ __launch_bounds__(128, 3) void cheb_gemm_tc(
    const float* __restrict__ Lmat,
    const __nv_bfloat16* __restrict__ BtHi,
    const __nv_bfloat16* __restrict__ BtLo,
    const float* __restrict__ Tpp,
    float* __restrict__ Tnew,
    float alpha, float beta)
{
    extern __shared__ __align__(16) char smem[];
    const uint32_t sb = smem_u32(smem);

    const int tid  = threadIdx.x;
    const int lane = tid & 31;
    const int wid  = tid >> 5;
    const int b    = blockIdx.y;
    const int row0 = blockIdx.x * BM;

    const float* Lb = Lmat + ((size_t)b * NN + row0) * NN;
    const __nv_bfloat16* bhsrc = BtHi + (size_t)b * FF * NN;
    const __nv_bfloat16* blsrc = BtLo + (size_t)b * FF * NN;

    // issue stage for chunk c
    auto issue = [&](int c) {
        const uint32_t st = sb + (uint32_t)(c % NSTAGE) * STAGE_BYTES;
        const int k0 = c * KC;
#pragma unroll
        for (int i = 0; i < 4; i++) {
            const int idx = i * 128 + tid;          // 0..511 16B chunks
            const int r = idx >> 3, g = idx & 7;
            cp16(st + r * AROWB + g * 16, Lb + (size_t)r * NN + k0 + g * 4);
        }
        const int f = tid >> 2, g = tid & 3;
        cp16(st + BHI_OFF + f * BROWB + g * 16, bhsrc + (size_t)f * NN + k0 + g * 8);
        cp16(st + BLO_OFF + f * BROWB + g * 16, blsrc + (size_t)f * NN + k0 + g * 8);
    };

    // prologue: stages 0..NSTAGE-2
#pragma unroll
    for (int s = 0; s < NSTAGE - 1; s++) { issue(s); CP_COMMIT(); }

    float acc[4][4];
#pragma unroll
    for (int i = 0; i < 4; i++)
#pragma unroll
        for (int j = 0; j < 4; j++) acc[i][j] = 0.0f;

    const int rsub = (lane >> 2);        // 0..7
    const int kq   = (lane & 3) * 2;     // 0,2,4,6

    for (int i = 0; i < NCHUNK; i++) {
        CP_WAIT(NSTAGE - 2);
        __syncthreads();
        if (i + NSTAGE - 1 < NCHUNK) issue(i + NSTAGE - 1);
        CP_COMMIT();

        const char* st = smem + (i % NSTAGE) * STAGE_BYTES;
        const float* As = (const float*)st;

#pragma unroll
        for (int kf = 0; kf < 2; kf++) {
            const int kb = kf * 16;
            const float* Ap = As + (wid * 16 + rsub) * AROWF + kb + kq;
            const float2 p0 = *(const float2*)(Ap);
            const float2 p1 = *(const float2*)(Ap + 8 * AROWF);
            const float2 p2 = *(const float2*)(Ap + 8);
            const float2 p3 = *(const float2*)(Ap + 8 * AROWF + 8);

            uint32_t ah0, ah1, ah2, ah3, al0, al1, al2, al3;
            split2(p0.x, p0.y, ah0, al0);
            split2(p1.x, p1.y, ah1, al1);
            split2(p2.x, p2.y, ah2, al2);
            split2(p3.x, p3.y, ah3, al3);

#pragma unroll
            for (int nb = 0; nb < 4; nb++) {
                const int n = nb * 8 + rsub;
                const char* bp = st + BHI_OFF + n * BROWB + (kb + kq) * 2;
                const uint32_t bh0 = *(const uint32_t*)(bp);
                const uint32_t bh1 = *(const uint32_t*)(bp + 16);
                const uint32_t bl0 = *(const uint32_t*)(bp + (BLO_OFF - BHI_OFF));
                const uint32_t bl1 = *(const uint32_t*)(bp + (BLO_OFF - BHI_OFF) + 16);

                mma16816(acc[nb], ah0, ah1, ah2, ah3, bh0, bh1);  // hi*hi
                mma16816(acc[nb], ah0, ah1, ah2, ah3, bl0, bl1);  // hi*lo
                mma16816(acc[nb], al0, al1, al2, al3, bh0, bh1);  // lo*hi
            }
        }
    }

    // epilogue: Tnew = alpha*acc + beta*Tpp
    const int rA = row0 + wid * 16 + rsub;
#pragma unroll
    for (int nb = 0; nb < 4; nb++) {
        const int col = nb * 8 + kq;
        const size_t o0 = ((size_t)b * NN + rA) * FF + col;
        const size_t o1 = o0 + 8 * FF;
        float2 v0 = make_float2(alpha * acc[nb][0], alpha * acc[nb][1]);
        float2 v1 = make_float2(alpha * acc[nb][2], alpha * acc[nb][3]);
        if (beta != 0.0f) {
            const float2 q0 = *(const float2*)(Tpp + o0);
            const float2 q1 = *(const float2*)(Tpp + o1);
            v0.x += beta * q0.x; v0.y += beta * q0.y;
            v1.x += beta * q1.x; v1.y += beta * q1.y;
        }
        *(float2*)(Tnew + o0) = v0;
        *(float2*)(Tnew + o1) = v1;
    }
}

// ---------------------------------------------------------------------------
// Projection: out[b,n,:] (+)= theta[k] * T[b,n,:] @ W[k]
// ---------------------------------------------------------------------------
#define PROWS 16

__global__ __launch_bounds__(128) void cheb_proj(
    const float* __restrict__ T,
    const float* __restrict__ W,
    const float* __restrict__ theta,
    int k,
    float* __restrict__ out,
    int accumulate)
{
    __shared__ float Ts[PROWS][FF];

    const int o = threadIdx.x;
    const size_t rowBase = (size_t)blockIdx.x * PROWS;
    const float* Wk = W + (size_t)k * FF * OO;

    float w[FF];
#pragma unroll
    for (int f = 0; f < FF; f++) w[f] = Wk[(size_t)f * OO + o];

    for (int i = threadIdx.x; i < PROWS * FF; i += 128) {
        (&Ts[0][0])[i] = T[rowBase * FF + i];
    }
    __syncthreads();

    const float th = theta[k];
#pragma unroll
    for (int r = 0; r < PROWS; r++) {
        float a = 0.0f;
#pragma unroll
        for (int f = 0; f < FF; f++) a += Ts[r][f] * w[f];
        const size_t oidx = (rowBase + r) * OO + o;
        float v = th * a;
        if (accumulate) v += out[oidx];
        out[oidx] = v;
    }
}

// ---------------------------------------------------------------------------
// Launcher
// ---------------------------------------------------------------------------
extern "C" void kernel_launch(void* const* d_in, const int* in_sizes, int n_in,
                              void* d_out, int out_size)
{
    const float* x = nullptr;
    const float* Lm = nullptr;
    const float* W = nullptr;
    const float* theta = nullptr;
    for (int i = 0; i < n_in; i++) {
        switch (in_sizes[i]) {
            case BB * NN * FF: x = (const float*)d_in[i]; break;
            case BB * NN * NN: Lm = (const float*)d_in[i]; break;
            case KK * FF * OO: W = (const float*)d_in[i]; break;
            case KK:           theta = (const float*)d_in[i]; break;
            default: break;
        }
    }
    float* out = (float*)d_out;

    float *bufA = nullptr, *bufB = nullptr;
    __nv_bfloat16 *btHi = nullptr, *btLo = nullptr;
    cudaGetSymbolAddress((void**)&bufA, g_bufA);
    cudaGetSymbolAddress((void**)&bufB, g_bufB);
    cudaGetSymbolAddress((void**)&btHi, g_bt_hi);
    cudaGetSymbolAddress((void**)&btLo, g_bt_lo);

    cudaFuncSetAttribute(cheb_gemm_tc, cudaFuncAttributeMaxDynamicSharedMemorySize, SMEM_TOTAL);

    const dim3 gGrid(NN / BM, BB);
    const dim3 pGrid((BB * NN) / PROWS);
    const dim3 bGrid((BB * FF * NN) / 256);

    // k = 0
    cheb_proj<<<pGrid, 128>>>(x, W, theta, 0, out, 0);
    prep_b<<<bGrid, 256>>>(x, btHi, btLo);

    // T1 = L @ x
    cheb_gemm_tc<<<gGrid, 128, SMEM_TOTAL>>>(Lm, btHi, btLo, x, bufA, 1.0f, 0.0f);
    cheb_proj<<<pGrid, 128>>>(bufA, W, theta, 1, out, 1);
    prep_b<<<bGrid, 256>>>(bufA, btHi, btLo);

    // T2 = 2 L @ T1 - x
    cheb_gemm_tc<<<gGrid, 128, SMEM_TOTAL>>>(Lm, btHi, btLo, x, bufB, 2.0f, -1.0f);
    cheb_proj<<<pGrid, 128>>>(bufB, W, theta, 2, out, 1);
    prep_b<<<bGrid, 256>>>(bufB, btHi, btLo);

    // T3 = 2 L @ T2 - T1  (write bufA; Tpp=bufA same-index, safe)
    cheb_gemm_tc<<<gGrid, 128, SMEM_TOTAL>>>(Lm, btHi, btLo, bufA, bufA, 2.0f, -1.0f);
    cheb_proj<<<pGrid, 128>>>(bufA, W, theta, 3, out, 1);
    prep_b<<<bGrid, 256>>>(bufA, btHi, btLo);

    // T4 = 2 L @ T3 - T2
    cheb_gemm_tc<<<gGrid, 128, SMEM_TOTAL>>>(Lm, btHi, btLo, bufB, bufB, 2.0f, -1.0f);
    cheb_proj<<<pGrid, 128>>>(bufB, W, theta, 4, out, 1);
    prep_b<<<bGrid, 256>>>(bufB, btHi, btLo);

    // T5 = 2 L @ T4 - T3
    cheb_gemm_tc<<<gGrid, 128, SMEM_TOTAL>>>(Lm, btHi, btLo, bufA, bufA, 2.0f, -1.0f);
    cheb_proj<<<pGrid, 128>>>(bufA, W, theta, 5, out, 1);
}

// round 4
// speedup vs baseline: 3.0604x; 1.1424x over previous
#include <cuda_runtime.h>
#include <cuda_bf16.h>
#include <cstdint>

#define BB 4
#define NN 4096
#define FF 32
#define KK 6
#define OO 128

// ---- GEMM tiling ----
#define BM 64                   // rows per CTA (4 warps x 16 rows)
#define KC 32                   // k per chunk
#define NSTAGE 4
#define NCHUNK (NN / KC)        // 128

#define AROWF 40                                // A smem row stride in floats
#define AROWB (AROWF * 4)
#define A_BYTES (BM * AROWB)                    // 10240
#define BROWB 80                                // B smem row stride bytes
#define B_BYTES (FF * BROWB)                    // 2560
#define BHI_OFF A_BYTES
#define BLO_OFF (A_BYTES + B_BYTES)
#define STAGE_BYTES (A_BYTES + 2 * B_BYTES)     // 15360
#define SMEM_TOTAL (NSTAGE * STAGE_BYTES)       // 61440

// ---- scratch ----
// fp32 recurrence ping-pong
__device__ float g_bufA[BB * NN * FF];
__device__ float g_bufB[BB * NN * FF];
// GEMM B operand: transposed [b][f][n] bf16 hi/lo, double buffered
__device__ __nv_bfloat16 g_btg_hi[2][BB * FF * NN];
__device__ __nv_bfloat16 g_btg_lo[2][BB * FF * NN];
// Projection slab: [b*N][K*F = 192] bf16 hi/lo (slot k at cols k*32..)
#define PK (KK * FF)            // 192
__device__ __nv_bfloat16 g_btp_hi[(size_t)BB * NN * PK];
__device__ __nv_bfloat16 g_btp_lo[(size_t)BB * NN * PK];
// W' = theta_k * W_k, layout [o][k6*32+f], bf16 hi/lo
__device__ __nv_bfloat16 g_wt_hi[OO * PK];
__device__ __nv_bfloat16 g_wt_lo[OO * PK];

__device__ __forceinline__ uint32_t smem_u32(const void* p) {
    uint32_t a;
    asm("{ .reg .u64 t; cvta.to.shared.u64 t, %1; cvt.u32.u64 %0, t; }" : "=r"(a) : "l"(p));
    return a;
}
__device__ __forceinline__ void cp16(uint32_t dst, const void* src) {
    asm volatile("cp.async.cg.shared.global [%0], [%1], 16;" :: "r"(dst), "l"(src));
}
#define CP_COMMIT() asm volatile("cp.async.commit_group;" ::: "memory")
#define CP_WAIT(n)  asm volatile("cp.async.wait_group %0;" :: "n"(n) : "memory")

// rn-bf16 hi/lo split of a float pair; low half of packed reg = first element
__device__ __forceinline__ void split2(float x, float y, uint32_t& hi, uint32_t& lo) {
    asm("cvt.rn.bf16x2.f32 %0, %1, %2;" : "=r"(hi) : "f"(y), "f"(x));
    const float h0 = __uint_as_float(hi << 16);
    const float h1 = __uint_as_float(hi & 0xFFFF0000u);
    const float l0 = x - h0;
    const float l1 = y - h1;
    asm("cvt.rn.bf16x2.f32 %0, %1, %2;" : "=r"(lo) : "f"(l1), "f"(l0));
}

__device__ __forceinline__ void mma16816(float* c,
                                         uint32_t a0, uint32_t a1, uint32_t a2, uint32_t a3,
                                         uint32_t b0, uint32_t b1) {
    asm volatile(
        "mma.sync.aligned.m16n8k16.row.col.f32.bf16.bf16.f32 "
        "{%0,%1,%2,%3}, {%4,%5,%6,%7}, {%8,%9}, {%0,%1,%2,%3};"
        : "+f"(c[0]), "+f"(c[1]), "+f"(c[2]), "+f"(c[3])
        : "r"(a0), "r"(a1), "r"(a2), "r"(a3), "r"(b0), "r"(b1));
}

// ---------------------------------------------------------------------------
// Prep x: fp32 [b][n][f] -> btg[buf] ([b][f][n] hi/lo)  +  btp slot 0
// ---------------------------------------------------------------------------
__global__ __launch_bounds__(256) void prep_b(
    const float* __restrict__ T,
    __nv_bfloat16* __restrict__ gHi,
    __nv_bfloat16* __restrict__ gLo,
    __nv_bfloat16* __restrict__ pHi,
    __nv_bfloat16* __restrict__ pLo)
{
    const int idx = blockIdx.x * 256 + threadIdx.x;     // [b][f][n] flat
    const int n = idx & (NN - 1);
    const int f = (idx >> 12) & (FF - 1);
    const int b = idx >> 17;
    const float a = T[((size_t)b * NN + n) * FF + f];
    const __nv_bfloat16 h = __float2bfloat16_rn(a);
    const __nv_bfloat16 l = __float2bfloat16_rn(a - __bfloat162float(h));
    gHi[idx] = h;
    gLo[idx] = l;
    const size_t pidx = ((size_t)b * NN + n) * PK + f;  // slot 0
    pHi[pidx] = h;
    pLo[pidx] = l;
}

// ---------------------------------------------------------------------------
// Prep W': Wt[o][k6*32+f] = theta[k6] * W[k6][f][o], bf16 hi/lo
// ---------------------------------------------------------------------------
__global__ __launch_bounds__(256) void prep_w(
    const float* __restrict__ W,
    const float* __restrict__ theta,
    __nv_bfloat16* __restrict__ wHi,
    __nv_bfloat16* __restrict__ wLo)
{
    const int idx = blockIdx.x * 256 + threadIdx.x;     // 0 .. 192*128-1
    const int o  = idx & (OO - 1);
    const int kf = idx >> 7;        // 0..191
    const int k6 = kf >> 5;
    const float v = theta[k6] * W[(size_t)kf * OO + o];
    const __nv_bfloat16 h = __float2bfloat16_rn(v);
    const size_t w = (size_t)o * PK + kf;
    wHi[w] = h;
    wLo[w] = __float2bfloat16_rn(v - __bfloat162float(h));
}

// ---------------------------------------------------------------------------
// HMMA GEMM: Tnew = alpha * L @ Tprev + beta * Tpp, plus bf16 term export
// ---------------------------------------------------------------------------
__global__ __launch_bounds__(128, 3) void cheb_gemm_tc(
    const float* __restrict__ Lmat,
    const __nv_bfloat16* __restrict__ BtHi,
    const __nv_bfloat16* __restrict__ BtLo,
    const float* __restrict__ Tpp,
    float* __restrict__ Tnew,
    float alpha, float beta,
    __nv_bfloat16* __restrict__ outGHi,   // next-gemm layout [b][f][n]
    __nv_bfloat16* __restrict__ outGLo,
    __nv_bfloat16* __restrict__ outPHi,   // proj slab base (slot pre-offset NOT applied)
    __nv_bfloat16* __restrict__ outPLo,
    int pslot)
{
    extern __shared__ __align__(16) char smem[];
    const uint32_t sb = smem_u32(smem);

    const int tid  = threadIdx.x;
    const int lane = tid & 31;
    const int wid  = tid >> 5;
    const int b    = blockIdx.y;
    const int row0 = blockIdx.x * BM;

    const float* Lb = Lmat + ((size_t)b * NN + row0) * NN;
    const __nv_bfloat16* bhsrc = BtHi + (size_t)b * FF * NN;
    const __nv_bfloat16* blsrc = BtLo + (size_t)b * FF * NN;

    auto issue = [&](int c) {
        const uint32_t st = sb + (uint32_t)(c % NSTAGE) * STAGE_BYTES;
        const int k0 = c * KC;
#pragma unroll
        for (int i = 0; i < 4; i++) {
            const int idx = i * 128 + tid;
            const int r = idx >> 3, g = idx & 7;
            cp16(st + r * AROWB + g * 16, Lb + (size_t)r * NN + k0 + g * 4);
        }
        const int f = tid >> 2, g = tid & 3;
        cp16(st + BHI_OFF + f * BROWB + g * 16, bhsrc + (size_t)f * NN + k0 + g * 8);
        cp16(st + BLO_OFF + f * BROWB + g * 16, blsrc + (size_t)f * NN + k0 + g * 8);
    };

#pragma unroll
    for (int s = 0; s < NSTAGE - 1; s++) { issue(s); CP_COMMIT(); }

    float acc[4][4];
#pragma unroll
    for (int i = 0; i < 4; i++)
#pragma unroll
        for (int j = 0; j < 4; j++) acc[i][j] = 0.0f;

    const int rsub = (lane >> 2);
    const int kq   = (lane & 3) * 2;

    for (int i = 0; i < NCHUNK; i++) {
        CP_WAIT(NSTAGE - 2);
        __syncthreads();
        if (i + NSTAGE - 1 < NCHUNK) issue(i + NSTAGE - 1);
        CP_COMMIT();

        const char* st = smem + (i % NSTAGE) * STAGE_BYTES;
        const float* As = (const float*)st;

#pragma unroll
        for (int kf = 0; kf < 2; kf++) {
            const int kb = kf * 16;
            const float* Ap = As + (wid * 16 + rsub) * AROWF + kb + kq;
            const float2 p0 = *(const float2*)(Ap);
            const float2 p1 = *(const float2*)(Ap + 8 * AROWF);
            const float2 p2 = *(const float2*)(Ap + 8);
            const float2 p3 = *(const float2*)(Ap + 8 * AROWF + 8);

            uint32_t ah0, ah1, ah2, ah3, al0, al1, al2, al3;
            split2(p0.x, p0.y, ah0, al0);
            split2(p1.x, p1.y, ah1, al1);
            split2(p2.x, p2.y, ah2, al2);
            split2(p3.x, p3.y, ah3, al3);

#pragma unroll
            for (int nb = 0; nb < 4; nb++) {
                const int n = nb * 8 + rsub;
                const char* bp = st + BHI_OFF + n * BROWB + (kb + kq) * 2;
                const uint32_t bh0 = *(const uint32_t*)(bp);
                const uint32_t bh1 = *(const uint32_t*)(bp + 16);
                const uint32_t bl0 = *(const uint32_t*)(bp + (BLO_OFF - BHI_OFF));
                const uint32_t bl1 = *(const uint32_t*)(bp + (BLO_OFF - BHI_OFF) + 16);

                mma16816(acc[nb], ah0, ah1, ah2, ah3, bh0, bh1);
                mma16816(acc[nb], ah0, ah1, ah2, ah3, bl0, bl1);
                mma16816(acc[nb], al0, al1, al2, al3, bh0, bh1);
            }
        }
    }

    // epilogue: Tnew fp32 + btg [f][n] hi/lo + btp slab slot
    const int rA = row0 + wid * 16 + rsub;
#pragma unroll
    for (int nb = 0; nb < 4; nb++) {
        const int col = nb * 8 + kq;
        const size_t o0 = ((size_t)b * NN + rA) * FF + col;
        const size_t o1 = o0 + 8 * FF;
        float2 v0 = make_float2(alpha * acc[nb][0], alpha * acc[nb][1]);
        float2 v1 = make_float2(alpha * acc[nb][2], alpha * acc[nb][3]);
        if (beta != 0.0f) {
            const float2 q0 = *(const float2*)(Tpp + o0);
            const float2 q1 = *(const float2*)(Tpp + o1);
            v0.x += beta * q0.x; v0.y += beta * q0.y;
            v1.x += beta * q1.x; v1.y += beta * q1.y;
        }
        *(float2*)(Tnew + o0) = v0;
        *(float2*)(Tnew + o1) = v1;

        // bf16 splits (packed pairs along col)
        uint32_t h0, l0, h1, l1;
        split2(v0.x, v0.y, h0, l0);
        split2(v1.x, v1.y, h1, l1);

        // proj slab: [b*N + row][192], pair store at even col
        const size_t p0 = ((size_t)b * NN + rA) * PK + pslot * FF + col;
        const size_t p1 = p0 + 8 * PK;
        *(uint32_t*)(outPHi + p0) = h0;
        *(uint32_t*)(outPLo + p0) = l0;
        *(uint32_t*)(outPHi + p1) = h1;
        *(uint32_t*)(outPLo + p1) = l1;

        // next-gemm layout: [b][f][n]
        const size_t gA = ((size_t)b * FF + col) * NN;
        ((uint16_t*)outGHi)[gA + rA]           = (uint16_t)(h0 & 0xFFFF);
        ((uint16_t*)outGHi)[gA + NN + rA]      = (uint16_t)(h0 >> 16);
        ((uint16_t*)outGLo)[gA + rA]           = (uint16_t)(l0 & 0xFFFF);
        ((uint16_t*)outGLo)[gA + NN + rA]      = (uint16_t)(l0 >> 16);
        ((uint16_t*)outGHi)[gA + rA + 8]       = (uint16_t)(h1 & 0xFFFF);
        ((uint16_t*)outGHi)[gA + NN + rA + 8]  = (uint16_t)(h1 >> 16);
        ((uint16_t*)outGLo)[gA + rA + 8]       = (uint16_t)(l1 & 0xFFFF);
        ((uint16_t*)outGLo)[gA + NN + rA + 8]  = (uint16_t)(l1 >> 16);
    }
}

// ---------------------------------------------------------------------------
// Fused projection: out[16384,128] = A[16384,192] @ W'[192,128]  (HMMA, 3-prod)
// CTA: 64 rows x 64 o-cols, 256 threads (8 warps: 4 row-groups x 2 o-groups)
// ---------------------------------------------------------------------------
#define PJ_STRIDE 100   // u32 row stride (400 B, 16B-aligned, conflict-free)
#define PJ_SMEM (4 * 64 * PJ_STRIDE * 4)   // 102400 B

__global__ __launch_bounds__(256, 2) void proj_mma(
    const __nv_bfloat16* __restrict__ pHi,
    const __nv_bfloat16* __restrict__ pLo,
    const __nv_bfloat16* __restrict__ wHi,
    const __nv_bfloat16* __restrict__ wLo,
    float* __restrict__ out)
{
    extern __shared__ __align__(16) char smem[];
    uint32_t* Ah = (uint32_t*)smem;
    uint32_t* Al = Ah + 64 * PJ_STRIDE;
    uint32_t* Bh = Al + 64 * PJ_STRIDE;
    uint32_t* Bl = Bh + 64 * PJ_STRIDE;
    const uint32_t sAh = smem_u32(Ah), sAl = smem_u32(Al);
    const uint32_t sBh = smem_u32(Bh), sBl = smem_u32(Bl);

    const int tid = threadIdx.x;
    const int r0 = blockIdx.x * 64;          // flat row base in [0, B*N)
    const int oh = blockIdx.y;               // o half (0/1)

    // load A tile (64 rows x 384B) and B tile (64 o-rows x 384B), hi+lo
#pragma unroll
    for (int i = 0; i < 6; i++) {
        const int idx = i * 256 + tid;       // 0..1535
        const int row = idx / 24;
        const int ch  = idx % 24;
        cp16(sAh + row * 400 + ch * 16, pHi + (size_t)(r0 + row) * PK + ch * 8);
        cp16(sAl + row * 400 + ch * 16, pLo + (size_t)(r0 + row) * PK + ch * 8);
        cp16(sBh + row * 400 + ch * 16, wHi + (size_t)(oh * 64 + row) * PK + ch * 8);
        cp16(sBl + row * 400 + ch * 16, wLo + (size_t)(oh * 64 + row) * PK + ch * 8);
    }
    CP_COMMIT();
    CP_WAIT(0);
    __syncthreads();

    const int lane = tid & 31;
    const int wid  = tid >> 5;
    const int mw   = wid & 3;        // row group (16 rows)
    const int ow   = wid >> 2;       // o group (32 cols)
    const int rsub = lane >> 2;
    const int q    = lane & 3;

    float acc[4][4];
#pragma unroll
    for (int i = 0; i < 4; i++)
#pragma unroll
        for (int j = 0; j < 4; j++) acc[i][j] = 0.0f;

#pragma unroll
    for (int ki = 0; ki < 12; ki++) {
        const int kb2 = ki * 8;
        const uint32_t* Ar = Ah + (mw * 16 + rsub) * PJ_STRIDE + kb2 + q;
        const uint32_t* Alr = Al + (mw * 16 + rsub) * PJ_STRIDE + kb2 + q;
        const uint32_t ah0 = Ar[0],  ah1 = Ar[8 * PJ_STRIDE],  ah2 = Ar[4],  ah3 = Ar[8 * PJ_STRIDE + 4];
        const uint32_t al0 = Alr[0], al1 = Alr[8 * PJ_STRIDE], al2 = Alr[4], al3 = Alr[8 * PJ_STRIDE + 4];

#pragma unroll
        for (int nb = 0; nb < 4; nb++) {
            const int ob = ow * 32 + nb * 8 + rsub;
            const uint32_t* Br = Bh + ob * PJ_STRIDE + kb2 + q;
            const uint32_t* Blr = Bl + ob * PJ_STRIDE + kb2 + q;
            const uint32_t bh0 = Br[0], bh1 = Br[4];
            const uint32_t bl0 = Blr[0], bl1 = Blr[4];

            mma16816(acc[nb], ah0, ah1, ah2, ah3, bh0, bh1);
            mma16816(acc[nb], ah0, ah1, ah2, ah3, bl0, bl1);
            mma16816(acc[nb], al0, al1, al2, al3, bh0, bh1);
        }
    }

    const int row = r0 + mw * 16 + rsub;
#pragma unroll
    for (int nb = 0; nb < 4; nb++) {
        const int col = oh * 64 + ow * 32 + nb * 8 + q * 2;
        *(float2*)(out + (size_t)row * OO + col)       = make_float2(acc[nb][0], acc[nb][1]);
        *(float2*)(out + (size_t)(row + 8) * OO + col) = make_float2(acc[nb][2], acc[nb][3]);
    }
}

// ---------------------------------------------------------------------------
// Launcher
// ---------------------------------------------------------------------------
extern "C" void kernel_launch(void* const* d_in, const int* in_sizes, int n_in,
                              void* d_out, int out_size)
{
    const float* x = nullptr;
    const float* Lm = nullptr;
    const float* W = nullptr;
    const float* theta = nullptr;
    for (int i = 0; i < n_in; i++) {
        switch (in_sizes[i]) {
            case BB * NN * FF: x = (const float*)d_in[i]; break;
            case BB * NN * NN: Lm = (const float*)d_in[i]; break;
            case KK * FF * OO: W = (const float*)d_in[i]; break;
            case KK:           theta = (const float*)d_in[i]; break;
            default: break;
        }
    }
    float* out = (float*)d_out;

    float *bufA = nullptr, *bufB = nullptr;
    __nv_bfloat16 *btgHi = nullptr, *btgLo = nullptr;
    __nv_bfloat16 *btpHi = nullptr, *btpLo = nullptr;
    __nv_bfloat16 *wtHi = nullptr, *wtLo = nullptr;
    cudaGetSymbolAddress((void**)&bufA, g_bufA);
    cudaGetSymbolAddress((void**)&bufB, g_bufB);
    cudaGetSymbolAddress((void**)&btgHi, g_btg_hi);
    cudaGetSymbolAddress((void**)&btgLo, g_btg_lo);
    cudaGetSymbolAddress((void**)&btpHi, g_btp_hi);
    cudaGetSymbolAddress((void**)&btpLo, g_btp_lo);
    cudaGetSymbolAddress((void**)&wtHi, g_wt_hi);
    cudaGetSymbolAddress((void**)&wtLo, g_wt_lo);

    __nv_bfloat16* gHi[2] = { btgHi, btgHi + (size_t)BB * FF * NN };
    __nv_bfloat16* gLo[2] = { btgLo, btgLo + (size_t)BB * FF * NN };

    cudaFuncSetAttribute(cheb_gemm_tc, cudaFuncAttributeMaxDynamicSharedMemorySize, SMEM_TOTAL);
    cudaFuncSetAttribute(proj_mma, cudaFuncAttributeMaxDynamicSharedMemorySize, PJ_SMEM);

    const dim3 gGrid(NN / BM, BB);
    const dim3 bGrid((BB * FF * NN) / 256);
    const dim3 wGrid((PK * OO) / 256);
    const dim3 pjGrid((BB * NN) / 64, 2);

    prep_w<<<wGrid, 256>>>(W, theta, wtHi, wtLo);
    prep_b<<<bGrid, 256>>>(x, gHi[0], gLo[0], btpHi, btpLo);   // slot 0 = x

    // T1 = L @ x
    cheb_gemm_tc<<<gGrid, 128, SMEM_TOTAL>>>(Lm, gHi[0], gLo[0], x, bufA, 1.0f, 0.0f,
                                             gHi[1], gLo[1], btpHi, btpLo, 1);
    // T2 = 2 L @ T1 - x
    cheb_gemm_tc<<<gGrid, 128, SMEM_TOTAL>>>(Lm, gHi[1], gLo[1], x, bufB, 2.0f, -1.0f,
                                             gHi[0], gLo[0], btpHi, btpLo, 2);
    // T3 = 2 L @ T2 - T1
    cheb_gemm_tc<<<gGrid, 128, SMEM_TOTAL>>>(Lm, gHi[0], gLo[0], bufA, bufA, 2.0f, -1.0f,
                                             gHi[1], gLo[1], btpHi, btpLo, 3);
    // T4 = 2 L @ T3 - T2
    cheb_gemm_tc<<<gGrid, 128, SMEM_TOTAL>>>(Lm, gHi[1], gLo[1], bufB, bufB, 2.0f, -1.0f,
                                             gHi[0], gLo[0], btpHi, btpLo, 4);
    // T5 = 2 L @ T4 - T3
    cheb_gemm_tc<<<gGrid, 128, SMEM_TOTAL>>>(Lm, gHi[0], gLo[0], bufA, bufA, 2.0f, -1.0f,
                                             gHi[1], gLo[1], btpHi, btpLo, 5);

    // out = sum_k theta_k T_k W_k  (single HMMA GEMM)
    proj_mma<<<pjGrid, 256, PJ_SMEM>>>(btpHi, btpLo, wtHi, wtLo, out);
}

// round 5
// speedup vs baseline: 3.0642x; 1.0012x over previous
#include <cuda_runtime.h>
#include <cuda_bf16.h>
#include <cstdint>

#define BB 4
#define NN 4096
#define FF 32
#define KK 6
#define OO 128

// ---- GEMM tiling ----
#define BM 64                   // rows per CTA
#define KC 32                   // k per chunk
#define NSTAGE 6
#define NCHUNK (NN / KC)        // 128
#define GTHREADS 256            // 8 warps: 2 k-groups x 4 row-groups

#define AROWF 40                                // A smem row stride in floats
#define AROWB (AROWF * 4)
#define A_BYTES (BM * AROWB)                    // 10240
#define BROWB 80                                // B smem row stride bytes
#define B_BYTES (FF * BROWB)                    // 2560
#define BHI_OFF A_BYTES
#define BLO_OFF (A_BYTES + B_BYTES)
#define STAGE_BYTES (A_BYTES + 2 * B_BYTES)     // 15360
#define SMEM_TOTAL (NSTAGE * STAGE_BYTES)       // 92160

#define RED_STRIDE 34                           // fp32 reduction buffer row stride

// ---- scratch ----
__device__ float g_bufA[BB * NN * FF];
__device__ float g_bufB[BB * NN * FF];
__device__ __nv_bfloat16 g_btg_hi[2][BB * FF * NN];
__device__ __nv_bfloat16 g_btg_lo[2][BB * FF * NN];
#define PK (KK * FF)            // 192
__device__ __nv_bfloat16 g_btp_hi[(size_t)BB * NN * PK];
__device__ __nv_bfloat16 g_btp_lo[(size_t)BB * NN * PK];
__device__ __nv_bfloat16 g_wt_hi[OO * PK];
__device__ __nv_bfloat16 g_wt_lo[OO * PK];

__device__ __forceinline__ uint32_t smem_u32(const void* p) {
    uint32_t a;
    asm("{ .reg .u64 t; cvta.to.shared.u64 t, %1; cvt.u32.u64 %0, t; }" : "=r"(a) : "l"(p));
    return a;
}
__device__ __forceinline__ void cp16(uint32_t dst, const void* src) {
    asm volatile("cp.async.cg.shared.global [%0], [%1], 16;" :: "r"(dst), "l"(src));
}
#define CP_COMMIT() asm volatile("cp.async.commit_group;" ::: "memory")
#define CP_WAIT(n)  asm volatile("cp.async.wait_group %0;" :: "n"(n) : "memory")

__device__ __forceinline__ void split2(float x, float y, uint32_t& hi, uint32_t& lo) {
    asm("cvt.rn.bf16x2.f32 %0, %1, %2;" : "=r"(hi) : "f"(y), "f"(x));
    const float h0 = __uint_as_float(hi << 16);
    const float h1 = __uint_as_float(hi & 0xFFFF0000u);
    const float l0 = x - h0;
    const float l1 = y - h1;
    asm("cvt.rn.bf16x2.f32 %0, %1, %2;" : "=r"(lo) : "f"(l1), "f"(l0));
}

__device__ __forceinline__ void mma16816(float* c,
                                         uint32_t a0, uint32_t a1, uint32_t a2, uint32_t a3,
                                         uint32_t b0, uint32_t b1) {
    asm volatile(
        "mma.sync.aligned.m16n8k16.row.col.f32.bf16.bf16.f32 "
        "{%0,%1,%2,%3}, {%4,%5,%6,%7}, {%8,%9}, {%0,%1,%2,%3};"
        : "+f"(c[0]), "+f"(c[1]), "+f"(c[2]), "+f"(c[3])
        : "r"(a0), "r"(a1), "r"(a2), "r"(a3), "r"(b0), "r"(b1));
}

// ---------------------------------------------------------------------------
// Prep x: fp32 [b][n][f] -> btg ([b][f][n] hi/lo)  +  btp slot 0
// ---------------------------------------------------------------------------
__global__ __launch_bounds__(256) void prep_b(
    const float* __restrict__ T,
    __nv_bfloat16* __restrict__ gHi,
    __nv_bfloat16* __restrict__ gLo,
    __nv_bfloat16* __restrict__ pHi,
    __nv_bfloat16* __restrict__ pLo)
{
    const int idx = blockIdx.x * 256 + threadIdx.x;
    const int n = idx & (NN - 1);
    const int f = (idx >> 12) & (FF - 1);
    const int b = idx >> 17;
    const float a = T[((size_t)b * NN + n) * FF + f];
    const __nv_bfloat16 h = __float2bfloat16_rn(a);
    const __nv_bfloat16 l = __float2bfloat16_rn(a - __bfloat162float(h));
    gHi[idx] = h;
    gLo[idx] = l;
    const size_t pidx = ((size_t)b * NN + n) * PK + f;
    pHi[pidx] = h;
    pLo[pidx] = l;
}

// ---------------------------------------------------------------------------
// Prep W': Wt[o][k6*32+f] = theta[k6] * W[k6][f][o], bf16 hi/lo
// ---------------------------------------------------------------------------
__global__ __launch_bounds__(256) void prep_w(
    const float* __restrict__ W,
    const float* __restrict__ theta,
    __nv_bfloat16* __restrict__ wHi,
    __nv_bfloat16* __restrict__ wLo)
{
    const int idx = blockIdx.x * 256 + threadIdx.x;
    const int o  = idx & (OO - 1);
    const int kf = idx >> 7;
    const int k6 = kf >> 5;
    const float v = theta[k6] * W[(size_t)kf * OO + o];
    const __nv_bfloat16 h = __float2bfloat16_rn(v);
    const size_t w = (size_t)o * PK + kf;
    wHi[w] = h;
    wLo[w] = __float2bfloat16_rn(v - __bfloat162float(h));
}

// ---------------------------------------------------------------------------
// HMMA GEMM, 256 threads, k-split across 2 warp groups + smem reduction.
// Tnew = alpha * L @ Tprev + beta * Tpp, plus bf16 term export.
// ---------------------------------------------------------------------------
__global__ __launch_bounds__(GTHREADS, 2) void cheb_gemm_tc(
    const float* __restrict__ Lmat,
    const __nv_bfloat16* __restrict__ BtHi,
    const __nv_bfloat16* __restrict__ BtLo,
    const float* __restrict__ Tpp,
    float* __restrict__ Tnew,
    float alpha, float beta,
    __nv_bfloat16* __restrict__ outGHi,
    __nv_bfloat16* __restrict__ outGLo,
    __nv_bfloat16* __restrict__ outPHi,
    __nv_bfloat16* __restrict__ outPLo,
    int pslot)
{
    extern __shared__ __align__(16) char smem[];
    const uint32_t sb = smem_u32(smem);

    const int tid  = threadIdx.x;
    const int lane = tid & 31;
    const int wid  = tid >> 5;
    const int wg   = wid >> 2;       // k-group: 0 -> k0..15, 1 -> k16..31
    const int wl   = wid & 3;        // row group (16 rows)
    const int b    = blockIdx.y;
    const int row0 = blockIdx.x * BM;

    const float* Lb = Lmat + ((size_t)b * NN + row0) * NN;
    const __nv_bfloat16* bhsrc = BtHi + (size_t)b * FF * NN;
    const __nv_bfloat16* blsrc = BtLo + (size_t)b * FF * NN;

    auto issue = [&](int c) {
        const uint32_t st = sb + (uint32_t)(c % NSTAGE) * STAGE_BYTES;
        const int k0 = c * KC;
        // A: 512 x 16B chunks, 2 per thread
#pragma unroll
        for (int i = 0; i < 2; i++) {
            const int idx = i * 256 + tid;
            const int r = idx >> 3, g = idx & 7;
            cp16(st + r * AROWB + g * 16, Lb + (size_t)r * NN + k0 + g * 4);
        }
        // B: hi by threads 0..127, lo by threads 128..255
        const int t2 = tid & 127;
        const int f = t2 >> 2, g = t2 & 3;
        if (tid < 128)
            cp16(st + BHI_OFF + f * BROWB + g * 16, bhsrc + (size_t)f * NN + k0 + g * 8);
        else
            cp16(st + BLO_OFF + f * BROWB + g * 16, blsrc + (size_t)f * NN + k0 + g * 8);
    };

#pragma unroll
    for (int s = 0; s < NSTAGE - 1; s++) { issue(s); CP_COMMIT(); }

    float acc[4][4];
#pragma unroll
    for (int i = 0; i < 4; i++)
#pragma unroll
        for (int j = 0; j < 4; j++) acc[i][j] = 0.0f;

    const int rsub = (lane >> 2);
    const int kq   = (lane & 3) * 2;
    const int kb   = wg * 16;        // this warp-group's k half

    for (int i = 0; i < NCHUNK; i++) {
        CP_WAIT(NSTAGE - 2);
        __syncthreads();
        if (i + NSTAGE - 1 < NCHUNK) issue(i + NSTAGE - 1);
        CP_COMMIT();

        const char* st = smem + (i % NSTAGE) * STAGE_BYTES;
        const float* As = (const float*)st;

        const float* Ap = As + (wl * 16 + rsub) * AROWF + kb + kq;
        const float2 p0 = *(const float2*)(Ap);
        const float2 p1 = *(const float2*)(Ap + 8 * AROWF);
        const float2 p2 = *(const float2*)(Ap + 8);
        const float2 p3 = *(const float2*)(Ap + 8 * AROWF + 8);

        uint32_t ah0, ah1, ah2, ah3, al0, al1, al2, al3;
        split2(p0.x, p0.y, ah0, al0);
        split2(p1.x, p1.y, ah1, al1);
        split2(p2.x, p2.y, ah2, al2);
        split2(p3.x, p3.y, ah3, al3);

#pragma unroll
        for (int nb = 0; nb < 4; nb++) {
            const int n = nb * 8 + rsub;
            const char* bp = st + BHI_OFF + n * BROWB + (kb + kq) * 2;
            const uint32_t bh0 = *(const uint32_t*)(bp);
            const uint32_t bh1 = *(const uint32_t*)(bp + 16);
            const uint32_t bl0 = *(const uint32_t*)(bp + (BLO_OFF - BHI_OFF));
            const uint32_t bl1 = *(const uint32_t*)(bp + (BLO_OFF - BHI_OFF) + 16);

            mma16816(acc[nb], ah0, ah1, ah2, ah3, bh0, bh1);
            mma16816(acc[nb], ah0, ah1, ah2, ah3, bl0, bl1);
            mma16816(acc[nb], al0, al1, al2, al3, bh0, bh1);
        }
    }

    // ---- cross-warp-group reduction (wg1 -> smem, wg0 adds) ----
    CP_WAIT(0);
    __syncthreads();
    float* red = (float*)smem;      // 64 x RED_STRIDE fp32 (8.7 KB), below stage-1 offset
    if (wg == 1) {
        const int r0l = wl * 16 + rsub;
#pragma unroll
        for (int nb = 0; nb < 4; nb++) {
            const int c0 = nb * 8 + kq;
            *(float2*)(red + r0l * RED_STRIDE + c0)       = make_float2(acc[nb][0], acc[nb][1]);
            *(float2*)(red + (r0l + 8) * RED_STRIDE + c0) = make_float2(acc[nb][2], acc[nb][3]);
        }
    }
    __syncthreads();

    if (wg == 0) {
        const int r0l = wl * 16 + rsub;
#pragma unroll
        for (int nb = 0; nb < 4; nb++) {
            const int c0 = nb * 8 + kq;
            const float2 q0 = *(const float2*)(red + r0l * RED_STRIDE + c0);
            const float2 q1 = *(const float2*)(red + (r0l + 8) * RED_STRIDE + c0);
            acc[nb][0] += q0.x; acc[nb][1] += q0.y;
            acc[nb][2] += q1.x; acc[nb][3] += q1.y;
        }

        // ---- epilogue: Tnew fp32 + btg [f][n] hi/lo + btp slab slot ----
        const int rA = row0 + wl * 16 + rsub;
#pragma unroll
        for (int nb = 0; nb < 4; nb++) {
            const int col = nb * 8 + kq;
            const size_t o0 = ((size_t)b * NN + rA) * FF + col;
            const size_t o1 = o0 + 8 * FF;
            float2 v0 = make_float2(alpha * acc[nb][0], alpha * acc[nb][1]);
            float2 v1 = make_float2(alpha * acc[nb][2], alpha * acc[nb][3]);
            if (beta != 0.0f) {
                const float2 q0 = *(const float2*)(Tpp + o0);
                const float2 q1 = *(const float2*)(Tpp + o1);
                v0.x += beta * q0.x; v0.y += beta * q0.y;
                v1.x += beta * q1.x; v1.y += beta * q1.y;
            }
            *(float2*)(Tnew + o0) = v0;
            *(float2*)(Tnew + o1) = v1;

            uint32_t h0, l0, h1, l1;
            split2(v0.x, v0.y, h0, l0);
            split2(v1.x, v1.y, h1, l1);

            const size_t p0 = ((size_t)b * NN + rA) * PK + pslot * FF + col;
            const size_t p1 = p0 + 8 * PK;
            *(uint32_t*)(outPHi + p0) = h0;
            *(uint32_t*)(outPLo + p0) = l0;
            *(uint32_t*)(outPHi + p1) = h1;
            *(uint32_t*)(outPLo + p1) = l1;

            const size_t gA = ((size_t)b * FF + col) * NN;
            ((uint16_t*)outGHi)[gA + rA]           = (uint16_t)(h0 & 0xFFFF);
            ((uint16_t*)outGHi)[gA + NN + rA]      = (uint16_t)(h0 >> 16);
            ((uint16_t*)outGLo)[gA + rA]           = (uint16_t)(l0 & 0xFFFF);
            ((uint16_t*)outGLo)[gA + NN + rA]      = (uint16_t)(l0 >> 16);
            ((uint16_t*)outGHi)[gA + rA + 8]       = (uint16_t)(h1 & 0xFFFF);
            ((uint16_t*)outGHi)[gA + NN + rA + 8]  = (uint16_t)(h1 >> 16);
            ((uint16_t*)outGLo)[gA + rA + 8]       = (uint16_t)(l1 & 0xFFFF);
            ((uint16_t*)outGLo)[gA + NN + rA + 8]  = (uint16_t)(l1 >> 16);
        }
    }
}

// ---------------------------------------------------------------------------
// Fused projection: out[16384,128] = A[16384,192] @ W'[192,128]
// ---------------------------------------------------------------------------
#define PJ_STRIDE 100
#define PJ_SMEM (4 * 64 * PJ_STRIDE * 4)

__global__ __launch_bounds__(256, 2) void proj_mma(
    const __nv_bfloat16* __restrict__ pHi,
    const __nv_bfloat16* __restrict__ pLo,
    const __nv_bfloat16* __restrict__ wHi,
    const __nv_bfloat16* __restrict__ wLo,
    float* __restrict__ out)
{
    extern __shared__ __align__(16) char smem[];
    uint32_t* Ah = (uint32_t*)smem;
    uint32_t* Al = Ah + 64 * PJ_STRIDE;
    uint32_t* Bh = Al + 64 * PJ_STRIDE;
    uint32_t* Bl = Bh + 64 * PJ_STRIDE;
    const uint32_t sAh = smem_u32(Ah), sAl = smem_u32(Al);
    const uint32_t sBh = smem_u32(Bh), sBl = smem_u32(Bl);

    const int tid = threadIdx.x;
    const int r0 = blockIdx.x * 64;
    const int oh = blockIdx.y;

#pragma unroll
    for (int i = 0; i < 6; i++) {
        const int idx = i * 256 + tid;
        const int row = idx / 24;
        const int ch  = idx % 24;
        cp16(sAh + row * 400 + ch * 16, pHi + (size_t)(r0 + row) * PK + ch * 8);
        cp16(sAl + row * 400 + ch * 16, pLo + (size_t)(r0 + row) * PK + ch * 8);
        cp16(sBh + row * 400 + ch * 16, wHi + (size_t)(oh * 64 + row) * PK + ch * 8);
        cp16(sBl + row * 400 + ch * 16, wLo + (size_t)(oh * 64 + row) * PK + ch * 8);
    }
    CP_COMMIT();
    CP_WAIT(0);
    __syncthreads();

    const int lane = tid & 31;
    const int wid  = tid >> 5;
    const int mw   = wid & 3;
    const int ow   = wid >> 2;
    const int rsub = lane >> 2;
    const int q    = lane & 3;

    float acc[4][4];
#pragma unroll
    for (int i = 0; i < 4; i++)
#pragma unroll
        for (int j = 0; j < 4; j++) acc[i][j] = 0.0f;

#pragma unroll
    for (int ki = 0; ki < 12; ki++) {
        const int kb2 = ki * 8;
        const uint32_t* Ar = Ah + (mw * 16 + rsub) * PJ_STRIDE + kb2 + q;
        const uint32_t* Alr = Al + (mw * 16 + rsub) * PJ_STRIDE + kb2 + q;
        const uint32_t ah0 = Ar[0],  ah1 = Ar[8 * PJ_STRIDE],  ah2 = Ar[4],  ah3 = Ar[8 * PJ_STRIDE + 4];
        const uint32_t al0 = Alr[0], al1 = Alr[8 * PJ_STRIDE], al2 = Alr[4], al3 = Alr[8 * PJ_STRIDE + 4];

#pragma unroll
        for (int nb = 0; nb < 4; nb++) {
            const int ob = ow * 32 + nb * 8 + rsub;
            const uint32_t* Br = Bh + ob * PJ_STRIDE + kb2 + q;
            const uint32_t* Blr = Bl + ob * PJ_STRIDE + kb2 + q;
            const uint32_t bh0 = Br[0], bh1 = Br[4];
            const uint32_t bl0 = Blr[0], bl1 = Blr[4];

            mma16816(acc[nb], ah0, ah1, ah2, ah3, bh0, bh1);
            mma16816(acc[nb], ah0, ah1, ah2, ah3, bl0, bl1);
            mma16816(acc[nb], al0, al1, al2, al3, bh0, bh1);
        }
    }

    const int row = r0 + mw * 16 + rsub;
#pragma unroll
    for (int nb = 0; nb < 4; nb++) {
        const int col = oh * 64 + ow * 32 + nb * 8 + q * 2;
        *(float2*)(out + (size_t)row * OO + col)       = make_float2(acc[nb][0], acc[nb][1]);
        *(float2*)(out + (size_t)(row + 8) * OO + col) = make_float2(acc[nb][2], acc[nb][3]);
    }
}

// ---------------------------------------------------------------------------
// Launcher
// ---------------------------------------------------------------------------
extern "C" void kernel_launch(void* const* d_in, const int* in_sizes, int n_in,
                              void* d_out, int out_size)
{
    const float* x = nullptr;
    const float* Lm = nullptr;
    const float* W = nullptr;
    const float* theta = nullptr;
    for (int i = 0; i < n_in; i++) {
        switch (in_sizes[i]) {
            case BB * NN * FF: x = (const float*)d_in[i]; break;
            case BB * NN * NN: Lm = (const float*)d_in[i]; break;
            case KK * FF * OO: W = (const float*)d_in[i]; break;
            case KK:           theta = (const float*)d_in[i]; break;
            default: break;
        }
    }
    float* out = (float*)d_out;

    float *bufA = nullptr, *bufB = nullptr;
    __nv_bfloat16 *btgHi = nullptr, *btgLo = nullptr;
    __nv_bfloat16 *btpHi = nullptr, *btpLo = nullptr;
    __nv_bfloat16 *wtHi = nullptr, *wtLo = nullptr;
    cudaGetSymbolAddress((void**)&bufA, g_bufA);
    cudaGetSymbolAddress((void**)&bufB, g_bufB);
    cudaGetSymbolAddress((void**)&btgHi, g_btg_hi);
    cudaGetSymbolAddress((void**)&btgLo, g_btg_lo);
    cudaGetSymbolAddress((void**)&btpHi, g_btp_hi);
    cudaGetSymbolAddress((void**)&btpLo, g_btp_lo);
    cudaGetSymbolAddress((void**)&wtHi, g_wt_hi);
    cudaGetSymbolAddress((void**)&wtLo, g_wt_lo);

    __nv_bfloat16* gHi[2] = { btgHi, btgHi + (size_t)BB * FF * NN };
    __nv_bfloat16* gLo[2] = { btgLo, btgLo + (size_t)BB * FF * NN };

    cudaFuncSetAttribute(cheb_gemm_tc, cudaFuncAttributeMaxDynamicSharedMemorySize, SMEM_TOTAL);
    cudaFuncSetAttribute(proj_mma, cudaFuncAttributeMaxDynamicSharedMemorySize, PJ_SMEM);

    const dim3 gGrid(NN / BM, BB);
    const dim3 bGrid((BB * FF * NN) / 256);
    const dim3 wGrid((PK * OO) / 256);
    const dim3 pjGrid((BB * NN) / 64, 2);

    prep_w<<<wGrid, 256>>>(W, theta, wtHi, wtLo);
    prep_b<<<bGrid, 256>>>(x, gHi[0], gLo[0], btpHi, btpLo);

    // T1 = L @ x
    cheb_gemm_tc<<<gGrid, GTHREADS, SMEM_TOTAL>>>(Lm, gHi[0], gLo[0], x, bufA, 1.0f, 0.0f,
                                                  gHi[1], gLo[1], btpHi, btpLo, 1);
    // T2 = 2 L @ T1 - x
    cheb_gemm_tc<<<gGrid, GTHREADS, SMEM_TOTAL>>>(Lm, gHi[1], gLo[1], x, bufB, 2.0f, -1.0f,
                                                  gHi[0], gLo[0], btpHi, btpLo, 2);
    // T3 = 2 L @ T2 - T1
    cheb_gemm_tc<<<gGrid, GTHREADS, SMEM_TOTAL>>>(Lm, gHi[0], gLo[0], bufA, bufA, 2.0f, -1.0f,
                                                  gHi[1], gLo[1], btpHi, btpLo, 3);
    // T4 = 2 L @ T3 - T2
    cheb_gemm_tc<<<gGrid, GTHREADS, SMEM_TOTAL>>>(Lm, gHi[1], gLo[1], bufB, bufB, 2.0f, -1.0f,
                                                  gHi[0], gLo[0], btpHi, btpLo, 4);
    // T5 = 2 L @ T4 - T3
    cheb_gemm_tc<<<gGrid, GTHREADS, SMEM_TOTAL>>>(Lm, gHi[0], gLo[0], bufA, bufA, 2.0f, -1.0f,
                                                  gHi[1], gLo[1], btpHi, btpLo, 5);

    // out = sum_k theta_k T_k W_k
    proj_mma<<<pjGrid, 256, PJ_SMEM>>>(btpHi, btpLo, wtHi, wtLo, out);
}